// round 10
// baseline (speedup 1.0000x reference)
#include <cuda_runtime.h>
#include <cstdint>
#include <math.h>

// Problem constants
#define B_   8
#define T_   4
#define C_   512
#define H_   32
#define W_   32
#define HW_  1024
#define BT_  32          // B_*T_
#define NPART 64         // channel partitions per t
#define CPP   (C_/NPART) // 8 channels per block
#define HP_  28
#define WP_  28
#define NP_  784         // 28*28
#define BN_EPS 1e-5f
#define BSTRIDE ((size_t)T_ * C_ * HW_)   // elements between consecutive b
#define BSTR4   (BSTRIDE/4)               // in float4 units
#define NTHR 512

// Dynamic smem: fp32 stage of current channel, both tensors.
// l: 2048 float4 (32 KB) then r: 2048 float4 (32 KB) = 65536 B.
#define STAGE_F4  2048
#define SMEM_DYN  (2 * STAGE_F4 * 16)

// Scratch (allocation-free rule: __device__ globals)
__device__ float g_part[NPART][BT_ * HW_];   // 8 MB
__device__ float g_d2_unused[4];             // (kept for ABI sanity)

// ---------------------------------------------------------------------------
// Fused kernel: ONE DRAM pass; current channel staged in SMEM (fp32), so the
// d^2 pass re-reads SMEM instead of L2 (removes 128 MB of LTS traffic) and no
// tile data is register-resident across the barrier (regs stay ~56).
// grid: T_*NPART = 256 blocks (2/SM), 512 threads.
// Per channel: load 4+4 float4 -> STS own slots -> stats sums from regs ->
// warp shuffle-reduce -> ONE barrier -> all-warp combine -> A,B,D ->
// LDS own slots (inline asm; no forwarding) -> accumulate d^2.
// beta cancels exactly in (l_bn - r_bn).
// ---------------------------------------------------------------------------
__global__ __launch_bounds__(NTHR, 2) void fused_kernel(
    const float* __restrict__ l, const float* __restrict__ r,
    const float* __restrict__ gamma)
{
    extern __shared__ float4 stage[];   // [0,2048)=l, [2048,4096)=r

    const int t   = blockIdx.x >> 6;        // / NPART
    const int p   = blockIdx.x & (NPART-1);
    const int tid = threadIdx.x;
    const int lane = tid & 31;
    const int wid  = tid >> 5;              // 0..15

    // This thread's 4 float4 slots: s_i = tid + i*512 -> (b, hw4)
    int bvec[4], hw4[4];
    size_t offb[4];
    #pragma unroll
    for (int i = 0; i < 4; i++) {
        const int s = tid + i * NTHR;
        bvec[i] = s >> 8;
        hw4[i]  = s & 255;
        offb[i] = (size_t)bvec[i] * BSTR4 + hw4[i];
    }

    unsigned int stage_base;
    asm("{ .reg .u64 tmp; cvta.to.shared.u64 tmp, %1; cvt.u32.u64 %0, tmp; }"
        : "=r"(stage_base) : "l"(stage));

    __shared__ float w0[2][16], w1[2][16], w2[2][16], w3[2][16];
    __shared__ float sgamma[CPP];
    if (tid < CPP) sgamma[tid] = gamma[p * CPP + tid];

    float acc[16];
    #pragma unroll
    for (int k = 0; k < 16; k++) acc[k] = 0.f;

    const float4* l4 = reinterpret_cast<const float4*>(l);
    const float4* r4 = reinterpret_cast<const float4*>(r);

    #pragma unroll 1
    for (int ci = 0; ci < CPP; ci++) {
        const int c = p * CPP + ci;
        const size_t chbase = ((size_t)(t * C_ + c)) * (HW_ / 4);

        // ---- load (front-batched), stage to smem, accumulate stats
        float4 lv[4], rv[4];
        #pragma unroll
        for (int i = 0; i < 4; i++) lv[i] = l4[offb[i] + chbase];
        #pragma unroll
        for (int i = 0; i < 4; i++) rv[i] = r4[offb[i] + chbase];
        #pragma unroll
        for (int i = 0; i < 4; i++) {
            stage[tid + i * NTHR]            = lv[i];
            stage[STAGE_F4 + tid + i * NTHR] = rv[i];
        }

        float sl = 0.f, ql = 0.f, sr = 0.f, qr = 0.f;
        #pragma unroll
        for (int i = 0; i < 4; i++) {
            sl += (lv[i].x + lv[i].y) + (lv[i].z + lv[i].w);
            sr += (rv[i].x + rv[i].y) + (rv[i].z + rv[i].w);
            ql = fmaf(lv[i].x, lv[i].x, ql); ql = fmaf(lv[i].y, lv[i].y, ql);
            ql = fmaf(lv[i].z, lv[i].z, ql); ql = fmaf(lv[i].w, lv[i].w, ql);
            qr = fmaf(rv[i].x, rv[i].x, qr); qr = fmaf(rv[i].y, rv[i].y, qr);
            qr = fmaf(rv[i].z, rv[i].z, qr); qr = fmaf(rv[i].w, rv[i].w, qr);
        }

        // ---- warp shuffle reduction
        #pragma unroll
        for (int o = 16; o > 0; o >>= 1) {
            sl += __shfl_xor_sync(0xffffffffu, sl, o);
            ql += __shfl_xor_sync(0xffffffffu, ql, o);
            sr += __shfl_xor_sync(0xffffffffu, sr, o);
            qr += __shfl_xor_sync(0xffffffffu, qr, o);
        }

        const int par = ci & 1;
        if (lane == 0) {
            w0[par][wid] = sl; w1[par][wid] = ql;
            w2[par][wid] = sr; w3[par][wid] = qr;
        }
        __syncthreads();   // the ONLY barrier per channel

        // ---- every warp combines the 16 warp-sums
        float a0 = (lane < 16) ? w0[par][lane] : 0.f;
        float a1 = (lane < 16) ? w1[par][lane] : 0.f;
        float a2 = (lane < 16) ? w2[par][lane] : 0.f;
        float a3 = (lane < 16) ? w3[par][lane] : 0.f;
        #pragma unroll
        for (int o = 8; o > 0; o >>= 1) {
            a0 += __shfl_xor_sync(0xffffffffu, a0, o);
            a1 += __shfl_xor_sync(0xffffffffu, a1, o);
            a2 += __shfl_xor_sync(0xffffffffu, a2, o);
            a3 += __shfl_xor_sync(0xffffffffu, a3, o);
        }
        a0 = __shfl_sync(0xffffffffu, a0, 0);
        a1 = __shfl_sync(0xffffffffu, a1, 0);
        a2 = __shfl_sync(0xffffffffu, a2, 0);
        a3 = __shfl_sync(0xffffffffu, a3, 0);

        const float inv_n = 1.f / (float)(B_ * HW_);   // 1/8192
        float mul  = a0 * inv_n;
        float mur  = a2 * inv_n;
        float varl = fmaf(-mul, mul, a1 * inv_n);
        float varr = fmaf(-mur, mur, a3 * inv_n);
        float g  = sgamma[ci];
        float A  = g / sqrtf(varl + BN_EPS);
        float Bc = g / sqrtf(varr + BN_EPS);
        float D  = A * mul - Bc * mur;

        // ---- d^2 pass: re-read own slots from SMEM (inline asm blocks
        //      register forwarding so lv/rv are dead across the barrier)
        #pragma unroll
        for (int i = 0; i < 4; i++) {
            const unsigned int aL = stage_base + (unsigned int)(tid + i * NTHR) * 16u;
            const unsigned int aR = aL + (unsigned int)(STAGE_F4 * 16);
            float4 sv, tv;
            asm volatile("ld.shared.v4.f32 {%0,%1,%2,%3}, [%4];"
                : "=f"(sv.x), "=f"(sv.y), "=f"(sv.z), "=f"(sv.w) : "r"(aL));
            asm volatile("ld.shared.v4.f32 {%0,%1,%2,%3}, [%4];"
                : "=f"(tv.x), "=f"(tv.y), "=f"(tv.z), "=f"(tv.w) : "r"(aR));
            float d;
            d = fmaf(A, sv.x, fmaf(-Bc, tv.x, -D)); acc[i*4+0] = fmaf(d, d, acc[i*4+0]);
            d = fmaf(A, sv.y, fmaf(-Bc, tv.y, -D)); acc[i*4+1] = fmaf(d, d, acc[i*4+1]);
            d = fmaf(A, sv.z, fmaf(-Bc, tv.z, -D)); acc[i*4+2] = fmaf(d, d, acc[i*4+2]);
            d = fmaf(A, sv.w, fmaf(-Bc, tv.w, -D)); acc[i*4+3] = fmaf(d, d, acc[i*4+3]);
        }
        // No barrier needed here: each thread only reuses its OWN stage slots
        // next iteration, and program order guarantees ST->LD within a thread.
    }

    // ---- write partials: g_part[p][(b*T+t)*1024 + hw] as float4
    float4* gp = reinterpret_cast<float4*>(g_part[p]);
    #pragma unroll
    for (int i = 0; i < 4; i++) {
        gp[(bvec[i] * T_ + t) * (HW_/4) + hw4[i]] =
            make_float4(acc[i*4+0], acc[i*4+1], acc[i*4+2], acc[i*4+3]);
    }
}

// ---------------------------------------------------------------------------
// Finalize (merged reduce+window+argmax/argmin):
// grid: 32 blocks (one per (b,t)), 1024 threads. Each thread sums the 64
// partial layers for its position (unrolled independent loads -> high MLP),
// then 5x5 window sum, sqrt, max + first-argmin.
// Output layout (float32, tuple order):
//   [0,32) values (B,T) | [32,96) coords (B,T,2) [x,y] | [96,25184) heatmap
// ---------------------------------------------------------------------------
__global__ __launch_bounds__(1024) void finalize_kernel(float* __restrict__ out)
{
    const int bt  = blockIdx.x;
    const int tid = threadIdx.x;

    __shared__ float d2[HW_];
    {
        float s0 = 0.f, s1 = 0.f, s2 = 0.f, s3 = 0.f;
        const int idx = bt * HW_ + tid;
        #pragma unroll
        for (int k = 0; k < NPART; k += 4) {
            s0 += g_part[k + 0][idx];
            s1 += g_part[k + 1][idx];
            s2 += g_part[k + 2][idx];
            s3 += g_part[k + 3][idx];
        }
        d2[tid] = (s0 + s1) + (s2 + s3);
    }
    __syncthreads();

    float mymax = -3.0e38f;
    float mymin =  3.0e38f;
    int   myidx = 0x7fffffff;

    if (tid < NP_) {
        const int y = tid / WP_;
        const int x = tid % WP_;
        float ws = 0.f;
        #pragma unroll
        for (int dy = 0; dy < 5; dy++)
            #pragma unroll
            for (int dx = 0; dx < 5; dx++)
                ws += d2[(y + dy) * W_ + (x + dx)];
        float hm = sqrtf(ws / 25.0f);
        out[96 + bt * NP_ + tid] = hm;
        mymax = hm; mymin = hm; myidx = tid;
    }

    __shared__ float smx[1024];
    __shared__ float smn[1024];
    __shared__ int   six[1024];
    smx[tid] = mymax; smn[tid] = mymin; six[tid] = myidx;
    __syncthreads();
    for (int st = 512; st > 0; st >>= 1) {
        if (tid < st) {
            smx[tid] = fmaxf(smx[tid], smx[tid + st]);
            float v = smn[tid + st];
            int  ix = six[tid + st];
            if (v < smn[tid] || (v == smn[tid] && ix < six[tid])) {
                smn[tid] = v; six[tid] = ix;
            }
        }
        __syncthreads();
    }

    if (tid == 0) {
        out[bt] = smx[0];
        int idx = six[0];
        out[32 + bt * 2 + 0] = (float)(idx % WP_);  // x_argmin
        out[32 + bt * 2 + 1] = (float)(idx / WP_);  // y_argmin
    }
}

// ---------------------------------------------------------------------------
extern "C" void kernel_launch(void* const* d_in, const int* in_sizes, int n_in,
                              void* d_out, int out_size)
{
    const float* l     = (const float*)d_in[0];
    const float* r     = (const float*)d_in[1];
    const float* gamma = (const float*)d_in[2];
    // d_in[3] = bn_beta: cancels exactly in (l_bn - r_bn), unused.
    float* out = (float*)d_out;

    static bool attr_set = false;
    if (!attr_set) {
        cudaFuncSetAttribute(fused_kernel,
            cudaFuncAttributeMaxDynamicSharedMemorySize, SMEM_DYN);
        attr_set = true;
    }

    fused_kernel<<<T_ * NPART, NTHR, SMEM_DYN>>>(l, r, gamma);
    finalize_kernel<<<BT_, 1024>>>(out);
}